// round 1
// baseline (speedup 1.0000x reference)
#include <cuda_runtime.h>
#include <cuda_bf16.h>
#include <math.h>

typedef unsigned long long ull;

#define NPROP   1000
#define FM_C    256
#define FM_HW   10000
#define POOLK   12544      // 49*256
#define HID     1024
#define NCLS    21
#define NFG     20
#define NCAND   20000      // NPROP * NFG
#define MAXDET  100

// ---------------- scratch (device globals; no allocation allowed) -------------
__device__ float  g_fmT[FM_HW * FM_C];          // [hw][c]  10.24MB
__device__ float  g_pooled[NPROP * POOLK];      // [n][cell*256+c] 50.2MB
__device__ float  g_part[2 * NPROP * HID];      // split-K partials 8MB
__device__ float  g_x1[NPROP * HID];
__device__ float  g_x2[NPROP * HID];
__device__ float  g_head[NPROP * 105];          // 21 logits + 84 deltas per row
__device__ float4 g_boxes[NCAND];
__device__ float4 g_boxoff[NCAND];
__device__ float  g_cand[NCAND];

// ---------------- helpers ------------------------------------------------------
__device__ __forceinline__ ull fma2(ull a, ull b, ull c) {
    ull d;
    asm("fma.rn.f32x2 %0, %1, %2, %3;" : "=l"(d) : "l"(a), "l"(b), "l"(c));
    return d;
}
__device__ __forceinline__ ull dup2(float a) {
    ull d;
    asm("mov.b64 %0, {%1, %1};" : "=l"(d) : "f"(a));
    return d;
}
union U64F2 { ull u; float2 f; };

// ---------------- 0: transpose feature map [256,10000] -> [10000,256] ----------
__global__ void transpose_fm(const float* __restrict__ fm) {
    __shared__ float tile[32][33];
    int hw0 = blockIdx.x * 32;
    int c0  = blockIdx.y * 32;
    int tx = threadIdx.x, ty = threadIdx.y;   // 32 x 8
#pragma unroll
    for (int j = 0; j < 32; j += 8) {
        int hw = hw0 + tx;
        float v = (hw < FM_HW) ? fm[(c0 + ty + j) * FM_HW + hw] : 0.f;
        tile[ty + j][tx] = v;
    }
    __syncthreads();
#pragma unroll
    for (int j = 0; j < 32; j += 8) {
        int hw = hw0 + ty + j;
        if (hw < FM_HW) g_fmT[hw * FM_C + c0 + tx] = tile[tx][ty + j];
    }
}

// ---------------- 1: ROI align -------------------------------------------------
// block = 64 threads (4 channels each, float4), one block per ROI
__global__ void roi_align_kernel(const float* __restrict__ rois) {
    int n = blockIdx.x;
    int t = threadIdx.x;      // 0..63
    float4 r = ((const float4*)rois)[n];
    float b0 = r.x * 0.125f - 0.5f;
    float b1 = r.y * 0.125f - 0.5f;
    float b2 = r.z * 0.125f - 0.5f;
    float b3 = r.w * 0.125f - 0.5f;
    float bw = (b2 - b0) / 7.0f;
    float bh = (b3 - b1) / 7.0f;

    __shared__ int   sx0[14], sx1[14], sy0[14], sy1[14];
    __shared__ float swx0[14], swx1[14], swy0[14], swy1[14], svx[14], svy[14];
    if (t < 14) {
        int p = t >> 1, s = t & 1;
        float off = (float)p + ((float)s + 0.5f) * 0.5f;
        // x axis
        float v = b0 + off * bw;
        svx[t] = (v >= -1.0f && v <= 100.0f) ? 1.f : 0.f;
        v = fminf(fmaxf(v, 0.f), 99.f);
        float v0 = floorf(v);
        int i0 = (int)v0;
        sx0[t] = i0; sx1[t] = min(i0 + 1, 99);
        swx1[t] = v - v0; swx0[t] = 1.f - (v - v0);
        // y axis
        v = b1 + off * bh;
        svy[t] = (v >= -1.0f && v <= 100.0f) ? 1.f : 0.f;
        v = fminf(fmaxf(v, 0.f), 99.f);
        v0 = floorf(v);
        i0 = (int)v0;
        sy0[t] = i0; sy1[t] = min(i0 + 1, 99);
        swy1[t] = v - v0; swy0[t] = 1.f - (v - v0);
    }
    __syncthreads();

    const float4* fmT4 = (const float4*)g_fmT;    // (y*100+x)*64 + t
    float4* outp = (float4*)(g_pooled + (size_t)n * POOLK);

    for (int ph = 0; ph < 7; ph++) {
        for (int pw = 0; pw < 7; pw++) {
            float ax = 0.f, ay = 0.f, az = 0.f, aw = 0.f;
#pragma unroll
            for (int sy = 0; sy < 2; sy++) {
                int j = ph * 2 + sy;
                int y0 = sy0[j], y1 = sy1[j];
                float wy0 = swy0[j], wy1 = swy1[j], vy = svy[j];
#pragma unroll
                for (int sx = 0; sx < 2; sx++) {
                    int k = pw * 2 + sx;
                    float m = vy * svx[k];
                    if (m != 0.f) {
                        int x0 = sx0[k], x1 = sx1[k];
                        float w00 = wy0 * swx0[k], w01 = wy0 * swx1[k];
                        float w10 = wy1 * swx0[k], w11 = wy1 * swx1[k];
                        float4 f00 = fmT4[(y0 * 100 + x0) * 64 + t];
                        float4 f01 = fmT4[(y0 * 100 + x1) * 64 + t];
                        float4 f10 = fmT4[(y1 * 100 + x0) * 64 + t];
                        float4 f11 = fmT4[(y1 * 100 + x1) * 64 + t];
                        ax += w00 * f00.x + w01 * f01.x + w10 * f10.x + w11 * f11.x;
                        ay += w00 * f00.y + w01 * f01.y + w10 * f10.y + w11 * f11.y;
                        az += w00 * f00.z + w01 * f01.z + w10 * f10.z + w11 * f11.z;
                        aw += w00 * f00.w + w01 * f01.w + w10 * f10.w + w11 * f11.w;
                    }
                }
            }
            float4 o = make_float4(ax * 0.25f, ay * 0.25f, az * 0.25f, aw * 0.25f);
            outp[(ph * 7 + pw) * 64 + t] = o;
        }
    }
}

// ---------------- 2: SGEMM with packed f32x2 FMA, split-K ----------------------
// C_partial[split][m*1024+n] = A[m, kslice] @ B[kslice, n]
// BM=128 BN=64 BK=16, 128 threads, 8x8 per thread.
#define BM 128
#define BN 64
#define BK 16

__global__ __launch_bounds__(128, 2)
void sgemm_kernel(const float* __restrict__ A, const float* __restrict__ B,
                  float* __restrict__ Cp,
                  int M, int N, int K, int lda, int ldb, int perm) {
    __shared__ float As[2][BK][BM];
    __shared__ float Bs[2][BK][BN];

    int t  = threadIdx.x;
    int tx = t & 7;            // 0..7  (N dir, 8 cols each)
    int ty = t >> 3;           // 0..15 (M dir, 8 rows each)
    int n0 = blockIdx.x * BN;
    int m0 = blockIdx.y * BM;
    int split = blockIdx.z;
    int nsplit = gridDim.z;
    int kLen = K / nsplit;
    int kb0  = split * kLen;
    int nkt  = kLen / BK;

    int m_load = m0 + t;
    bool mok = m_load < M;

    float4 aR[4];
    float4 bR[2];

    auto gload = [&](int kb) {
        const float* Arow = A + (size_t)m_load * lda + kb;
#pragma unroll
        for (int i = 0; i < 4; i++)
            aR[i] = mok ? *(const float4*)(Arow + i * 4) : make_float4(0, 0, 0, 0);
#pragma unroll
        for (int i = 0; i < 2; i++) {
            int id = t + i * 128;
            int krow = id >> 4;
            int col  = (id & 15) * 4;
            int brow = kb + krow;
            if (perm) brow = (brow & 255) * 49 + (brow >> 8);
            bR[i] = *(const float4*)(B + (size_t)brow * ldb + n0 + col);
        }
    };
    auto sstore = [&](int buf) {
#pragma unroll
        for (int i = 0; i < 4; i++) {
            As[buf][i * 4 + 0][t] = aR[i].x;
            As[buf][i * 4 + 1][t] = aR[i].y;
            As[buf][i * 4 + 2][t] = aR[i].z;
            As[buf][i * 4 + 3][t] = aR[i].w;
        }
#pragma unroll
        for (int i = 0; i < 2; i++) {
            int id = t + i * 128;
            int krow = id >> 4;
            int col  = (id & 15) * 4;
            *(float4*)&Bs[buf][krow][col] = bR[i];
        }
    };

    ull acc[8][4];
#pragma unroll
    for (int i = 0; i < 8; i++)
#pragma unroll
        for (int j = 0; j < 4; j++) acc[i][j] = 0ull;

    gload(kb0);
    sstore(0);
    __syncthreads();

    for (int kt = 0; kt < nkt; kt++) {
        if (kt + 1 < nkt) gload(kb0 + (kt + 1) * BK);
        int buf = kt & 1;
#pragma unroll
        for (int k = 0; k < BK; k++) {
            float4 a0 = *(const float4*)&As[buf][k][ty * 8];
            float4 a1 = *(const float4*)&As[buf][k][ty * 8 + 4];
            ull b0 = *(const ull*)&Bs[buf][k][tx * 8];
            ull b1 = *(const ull*)&Bs[buf][k][tx * 8 + 2];
            ull b2 = *(const ull*)&Bs[buf][k][tx * 8 + 4];
            ull b3 = *(const ull*)&Bs[buf][k][tx * 8 + 6];
            ull ax;
            ax = dup2(a0.x); acc[0][0]=fma2(ax,b0,acc[0][0]); acc[0][1]=fma2(ax,b1,acc[0][1]); acc[0][2]=fma2(ax,b2,acc[0][2]); acc[0][3]=fma2(ax,b3,acc[0][3]);
            ax = dup2(a0.y); acc[1][0]=fma2(ax,b0,acc[1][0]); acc[1][1]=fma2(ax,b1,acc[1][1]); acc[1][2]=fma2(ax,b2,acc[1][2]); acc[1][3]=fma2(ax,b3,acc[1][3]);
            ax = dup2(a0.z); acc[2][0]=fma2(ax,b0,acc[2][0]); acc[2][1]=fma2(ax,b1,acc[2][1]); acc[2][2]=fma2(ax,b2,acc[2][2]); acc[2][3]=fma2(ax,b3,acc[2][3]);
            ax = dup2(a0.w); acc[3][0]=fma2(ax,b0,acc[3][0]); acc[3][1]=fma2(ax,b1,acc[3][1]); acc[3][2]=fma2(ax,b2,acc[3][2]); acc[3][3]=fma2(ax,b3,acc[3][3]);
            ax = dup2(a1.x); acc[4][0]=fma2(ax,b0,acc[4][0]); acc[4][1]=fma2(ax,b1,acc[4][1]); acc[4][2]=fma2(ax,b2,acc[4][2]); acc[4][3]=fma2(ax,b3,acc[4][3]);
            ax = dup2(a1.y); acc[5][0]=fma2(ax,b0,acc[5][0]); acc[5][1]=fma2(ax,b1,acc[5][1]); acc[5][2]=fma2(ax,b2,acc[5][2]); acc[5][3]=fma2(ax,b3,acc[5][3]);
            ax = dup2(a1.z); acc[6][0]=fma2(ax,b0,acc[6][0]); acc[6][1]=fma2(ax,b1,acc[6][1]); acc[6][2]=fma2(ax,b2,acc[6][2]); acc[6][3]=fma2(ax,b3,acc[6][3]);
            ax = dup2(a1.w); acc[7][0]=fma2(ax,b0,acc[7][0]); acc[7][1]=fma2(ax,b1,acc[7][1]); acc[7][2]=fma2(ax,b2,acc[7][2]); acc[7][3]=fma2(ax,b3,acc[7][3]);
        }
        if (kt + 1 < nkt) {
            sstore(buf ^ 1);
            __syncthreads();
        }
    }

    float* Cout = Cp + (size_t)split * NPROP * HID;
#pragma unroll
    for (int i = 0; i < 8; i++) {
        int mrow = m0 + ty * 8 + i;
        if (mrow < M) {
            U64F2 u0, u1, u2, u3;
            u0.u = acc[i][0]; u1.u = acc[i][1]; u2.u = acc[i][2]; u3.u = acc[i][3];
            float4 c0 = make_float4(u0.f.x, u0.f.y, u1.f.x, u1.f.y);
            float4 c1 = make_float4(u2.f.x, u2.f.y, u3.f.x, u3.f.y);
            float* row = Cout + (size_t)mrow * HID + n0 + tx * 8;
            *(float4*)(row)     = c0;
            *(float4*)(row + 4) = c1;
        }
    }
}

// sum split-K partials + bias + relu
__global__ void fixup_relu(const float* __restrict__ p, const float* __restrict__ bias,
                           float* __restrict__ out) {
    int i = blockIdx.x * 256 + threadIdx.x;
    if (i < NPROP * HID) {
        float v = p[i] + p[NPROP * HID + i] + bias[i & (HID - 1)];
        out[i] = fmaxf(v, 0.f);
    }
}

// ---------------- 3: heads: x2 @ [wc | wb] + [bc | bb] -------------------------
__global__ void heads_kernel(const float* __restrict__ wc, const float* __restrict__ bc,
                             const float* __restrict__ wb, const float* __restrict__ bb) {
    __shared__ float xs[8 * HID];
    int m0 = blockIdx.x * 8;
    int t = threadIdx.x;    // 128
    const float4* src = (const float4*)(g_x2 + (size_t)m0 * HID);
    float4* dst = (float4*)xs;
    for (int i = t; i < 8 * HID / 4; i += 128) dst[i] = src[i];
    __syncthreads();
    if (t < 105) {
        float acc[8];
#pragma unroll
        for (int r = 0; r < 8; r++) acc[r] = 0.f;
        for (int k = 0; k < HID; k++) {
            float wv = (t < 21) ? wc[k * 21 + t] : wb[k * 84 + (t - 21)];
#pragma unroll
            for (int r = 0; r < 8; r++) acc[r] += xs[r * HID + k] * wv;
        }
        float bv = (t < 21) ? bc[t] : bb[t - 21];
#pragma unroll
        for (int r = 0; r < 8; r++) g_head[(size_t)(m0 + r) * 105 + t] = acc[r] + bv;
    }
}

// ---------------- 4: softmax + decode + candidate setup ------------------------
__global__ void postproc_kernel(const float* __restrict__ rois) {
    int m = blockIdx.x * 128 + threadIdx.x;
    if (m >= NPROP) return;
    const float* h = g_head + (size_t)m * 105;
    float lg[21];
    float mx = -INFINITY;
#pragma unroll
    for (int c = 0; c < 21; c++) { lg[c] = h[c]; mx = fmaxf(mx, lg[c]); }
    float sum = 0.f;
#pragma unroll
    for (int c = 0; c < 21; c++) { lg[c] = expf(lg[c] - mx); sum += lg[c]; }
    float inv = 1.0f / sum;

    float4 r = ((const float4*)rois)[m];
    float w  = r.z - r.x;
    float hh = r.w - r.y;
    float cx = r.x + 0.5f * w;
    float cy = r.y + 0.5f * hh;

#pragma unroll
    for (int c = 1; c < 21; c++) {
        float sc = lg[c] * inv;
        float dx = h[21 + (c - 1) * 0 + c * 4 + 0 - 4 + 4];  // placeholder avoided below
        // deltas for class c live at head cols 21 + c*4 .. 21 + c*4 + 3
        dx       = h[21 + c * 4 + 0];
        float dy = h[21 + c * 4 + 1];
        float dw = h[21 + c * 4 + 2];
        float dh = h[21 + c * 4 + 3];
        float pcx = dx * w + cx;
        float pcy = dy * hh + cy;
        float pw  = expf(dw) * w;
        float ph2 = expf(dh) * hh;
        float x1 = pcx - 0.5f * pw,  y1 = pcy - 0.5f * ph2;
        float x2 = pcx + 0.5f * pw,  y2 = pcy + 0.5f * ph2;
        int i = m * NFG + (c - 1);
        g_boxes[i]  = make_float4(x1, y1, x2, y2);
        float off = (float)c * 10000.0f;
        g_boxoff[i] = make_float4(x1 + off, y1 + off, x2 + off, y2 + off);
        g_cand[i] = (sc > 0.05f) ? sc : -1.0f;
    }
}

// ---------------- 5: sequential NMS (single block) -----------------------------
__global__ void nms_kernel(float* __restrict__ out) {
    extern __shared__ float s[];    // NCAND scores
    __shared__ float rv[32];
    __shared__ int   ri[32];
    __shared__ float4 pboxS;
    __shared__ int   keepI[MAXDET];
    __shared__ float keepV[MAXDET];
    int t = threadIdx.x;   // 1024
    for (int i = t; i < NCAND; i += 1024) s[i] = g_cand[i];
    __syncthreads();

    float4 pb = make_float4(0, 0, 0, 0);
    float parea = 0.f;
    bool have = false;

    for (int it = 0; it < MAXDET; it++) {
        float bv = -INFINITY;
        int bi = 0x7fffffff;
#pragma unroll
        for (int w = 0; w < 20; w++) {
            int i = t + (w << 10);
            if (i < NCAND) {
                float v = s[i];
                if (have && v > -INFINITY) {
                    float4 b = g_boxoff[i];
                    float ix1 = fmaxf(pb.x, b.x), iy1 = fmaxf(pb.y, b.y);
                    float ix2 = fminf(pb.z, b.z), iy2 = fminf(pb.w, b.w);
                    float inter = fmaxf(ix2 - ix1, 0.f) * fmaxf(iy2 - iy1, 0.f);
                    float A = (b.z - b.x) * (b.w - b.y);
                    float iou = inter / (parea + A - inter + 1e-9f);
                    if (iou > 0.5f) { v = -INFINITY; s[i] = v; }
                }
                if (v > bv || (v == bv && i < bi)) { bv = v; bi = i; }
            }
        }
#pragma unroll
        for (int o = 16; o; o >>= 1) {
            float ov = __shfl_down_sync(0xffffffffu, bv, o);
            int   oi = __shfl_down_sync(0xffffffffu, bi, o);
            if (ov > bv || (ov == bv && oi < bi)) { bv = ov; bi = oi; }
        }
        if ((t & 31) == 0) { rv[t >> 5] = bv; ri[t >> 5] = bi; }
        __syncthreads();
        if (t < 32) {
            bv = rv[t]; bi = ri[t];
#pragma unroll
            for (int o = 16; o; o >>= 1) {
                float ov = __shfl_down_sync(0xffffffffu, bv, o);
                int   oi = __shfl_down_sync(0xffffffffu, bi, o);
                if (ov > bv || (ov == bv && oi < bi)) { bv = ov; bi = oi; }
            }
            if (t == 0) {
                keepI[it] = bi;
                keepV[it] = bv;
                pboxS = g_boxoff[bi];
            }
        }
        __syncthreads();
        pb = pboxS;
        parea = (pb.z - pb.x) * (pb.w - pb.y);
        have = true;
    }
    __syncthreads();

    // output layout: [0:400) boxes, [400:500) scores, [500:600) labels(as float)
    if (t < MAXDET) {
        int ki = keepI[t];
        float ks = keepV[t];
        bool valid = ks > 0.05f;
        float4 b = g_boxes[ki];
        float vm = valid ? 1.f : 0.f;
        out[t * 4 + 0] = b.x * vm;
        out[t * 4 + 1] = b.y * vm;
        out[t * 4 + 2] = b.z * vm;
        out[t * 4 + 3] = b.w * vm;
        out[400 + t] = valid ? ks : 0.f;
        out[500 + t] = valid ? (float)((ki % NFG) + 1) : 0.f;
    }
}

__global__ void zero_out(float* out, int n) {
    int i = blockIdx.x * 256 + threadIdx.x;
    if (i < n) out[i] = 0.f;
}

// ---------------- launcher ------------------------------------------------------
extern "C" void kernel_launch(void* const* d_in, const int* in_sizes, int n_in,
                              void* d_out, int out_size) {
    const float* fm  = (const float*)d_in[0];
    const float* pr  = (const float*)d_in[1];
    const float* w1  = (const float*)d_in[2];
    const float* b1  = (const float*)d_in[3];
    const float* w2  = (const float*)d_in[4];
    const float* b2  = (const float*)d_in[5];
    const float* wc  = (const float*)d_in[6];
    const float* bc  = (const float*)d_in[7];
    const float* wb  = (const float*)d_in[8];
    const float* bb  = (const float*)d_in[9];
    float* out = (float*)d_out;

    float *pooled, *part, *x1, *x2;
    cudaGetSymbolAddress((void**)&pooled, g_pooled);
    cudaGetSymbolAddress((void**)&part,   g_part);
    cudaGetSymbolAddress((void**)&x1,     g_x1);
    cudaGetSymbolAddress((void**)&x2,     g_x2);

    zero_out<<<(out_size + 255) / 256, 256>>>(out, out_size);
    transpose_fm<<<dim3(313, 8), dim3(32, 8)>>>(fm);
    roi_align_kernel<<<NPROP, 64>>>(pr);

    // GEMM1: pooled[1000,12544] @ perm(w1)[12544,1024], split-K=2
    sgemm_kernel<<<dim3(HID / BN, (NPROP + BM - 1) / BM, 2), 128>>>(
        pooled, w1, part, NPROP, HID, POOLK, POOLK, HID, 1);
    fixup_relu<<<(NPROP * HID + 255) / 256, 256>>>(part, b1, x1);

    // GEMM2: x1[1000,1024] @ w2[1024,1024], split-K=2
    sgemm_kernel<<<dim3(HID / BN, (NPROP + BM - 1) / BM, 2), 128>>>(
        x1, w2, part, NPROP, HID, HID, HID, HID, 0);
    fixup_relu<<<(NPROP * HID + 255) / 256, 256>>>(part, b2, x2);

    heads_kernel<<<NPROP / 8, 128>>>(wc, bc, wb, bb);
    postproc_kernel<<<(NPROP + 127) / 128, 128>>>(pr);

    cudaFuncSetAttribute(nms_kernel, cudaFuncAttributeMaxDynamicSharedMemorySize,
                         NCAND * sizeof(float));
    nms_kernel<<<1, 1024, NCAND * sizeof(float)>>>(out);
}